// round 1
// baseline (speedup 1.0000x reference)
#include <cuda_runtime.h>
#include <math.h>
#include <stdint.h>

#define NN 50000
#define FEATS 128

// Scratch: aggregation buffer (25.6 MB) + index-width flag.
__device__ float g_agg[NN * FEATS];
__device__ int g_idx64;

// ---------------------------------------------------------------------------
// Detect whether src/dst are int64 or int32 (JAX may silently downcast).
// If the buffer is really int64, every 8-byte value is in [0, NN).
// If it is int32, the reinterpreted int64 values are ~always >= 2^32.
// ---------------------------------------------------------------------------
__global__ void detect_idx_kernel(const void* __restrict__ src) {
    const long long* p = (const long long*)src;
    int is64 = 1;
    for (int i = 0; i < 64; i++) {
        long long v = p[i];
        if (v < 0 || v >= NN) { is64 = 0; break; }
    }
    g_idx64 = is64;
}

// ---------------------------------------------------------------------------
// Zero the aggregation buffer (float4 stores).
// ---------------------------------------------------------------------------
__global__ void zero_agg_kernel() {
    int i = blockIdx.x * blockDim.x + threadIdx.x;
    if (i < NN * FEATS / 4) {
        ((float4*)g_agg)[i] = make_float4(0.f, 0.f, 0.f, 0.f);
    }
}

// ---------------------------------------------------------------------------
// Edge scatter: one warp per edge. Each lane handles 4 floats (float4).
// Vector reduction red.global.add.v4.f32 -> 1 REDG per lane per edge.
// ---------------------------------------------------------------------------
__global__ void scatter_kernel(const float* __restrict__ feat,
                               const void* __restrict__ src,
                               const void* __restrict__ dst,
                               int nEdges) {
    int gw = (blockIdx.x * blockDim.x + threadIdx.x) >> 5;
    if (gw >= nEdges) return;
    int lane = threadIdx.x & 31;

    int s, d;
    if (g_idx64) {
        s = (int)((const long long*)src)[gw];
        d = (int)((const long long*)dst)[gw];
    } else {
        s = ((const int*)src)[gw];
        d = ((const int*)dst)[gw];
    }

    float4 v = *(const float4*)(feat + s * FEATS + lane * 4);
    float* p = g_agg + d * FEATS + lane * 4;
    asm volatile("red.global.add.v4.f32 [%0], {%1, %2, %3, %4};"
                 :: "l"(p), "f"(v.x), "f"(v.y), "f"(v.z), "f"(v.w)
                 : "memory");
}

// ---------------------------------------------------------------------------
// Fused GEMM (out = tanh(agg @ W^T + b)).
// Persistent blocks: W loaded once per block into shared (transposed,
// row stride 132 floats so LDS.128 reads are conflict-free & 16B-aligned).
// Each block processes 32-node tiles; each warp computes 4 nodes,
// each lane computes 4 output columns (j0 = 4*lane).
// ---------------------------------------------------------------------------
#define WSH_STRIDE 132
#define TILE_N 32
#define GEMM_SMEM ((128 * WSH_STRIDE + TILE_N * FEATS) * 4)

__global__ __launch_bounds__(256) void gemm_tanh_kernel(
    const float* __restrict__ W, const float* __restrict__ b,
    float* __restrict__ out, int nNodes) {
    extern __shared__ float sh[];
    float* Wsh = sh;                       // [128][132]
    float* Ash = sh + 128 * WSH_STRIDE;    // [32][128]

    int tid = threadIdx.x;

    // Load W transposed: Wsh[k][j] = W[j][k]
    for (int idx = tid; idx < 128 * 128; idx += 256) {
        int j = idx >> 7;
        int k = idx & 127;
        Wsh[k * WSH_STRIDE + j] = W[idx];
    }

    int lane = tid & 31;
    int warp = tid >> 5;
    int j0 = lane * 4;
    float4 bias = *(const float4*)(b + j0);

    for (int tile = blockIdx.x * TILE_N; tile < nNodes; tile += gridDim.x * TILE_N) {
        __syncthreads();  // covers W-load on first iter; Ash reuse on later iters
        // Stage agg tile: 32 nodes x 128 floats (1024 float4, 4 iters/thread)
        for (int i = tid; i < TILE_N * (FEATS / 4); i += 256) {
            int n = i >> 5;
            int row = tile + n;
            if (row >= nNodes) row = nNodes - 1;
            int c = i & 31;
            ((float4*)Ash)[i] = ((const float4*)g_agg)[row * (FEATS / 4) + c];
        }
        __syncthreads();

        const float* a0 = Ash + (warp * 4 + 0) * FEATS;
        const float* a1 = a0 + FEATS;
        const float* a2 = a1 + FEATS;
        const float* a3 = a2 + FEATS;

        float4 c0 = make_float4(0.f, 0.f, 0.f, 0.f);
        float4 c1 = c0, c2 = c0, c3 = c0;

        #pragma unroll 8
        for (int k = 0; k < 128; k++) {
            float4 w = *(const float4*)(Wsh + k * WSH_STRIDE + j0);
            float x0 = a0[k], x1 = a1[k], x2 = a2[k], x3 = a3[k];
            c0.x = fmaf(w.x, x0, c0.x); c0.y = fmaf(w.y, x0, c0.y);
            c0.z = fmaf(w.z, x0, c0.z); c0.w = fmaf(w.w, x0, c0.w);
            c1.x = fmaf(w.x, x1, c1.x); c1.y = fmaf(w.y, x1, c1.y);
            c1.z = fmaf(w.z, x1, c1.z); c1.w = fmaf(w.w, x1, c1.w);
            c2.x = fmaf(w.x, x2, c2.x); c2.y = fmaf(w.y, x2, c2.y);
            c2.z = fmaf(w.z, x2, c2.z); c2.w = fmaf(w.w, x2, c2.w);
            c3.x = fmaf(w.x, x3, c3.x); c3.y = fmaf(w.y, x3, c3.y);
            c3.z = fmaf(w.z, x3, c3.z); c3.w = fmaf(w.w, x3, c3.w);
        }

        int nbase = tile + warp * 4;
        #define STORE_ROW(cc, off)                                                   \
            if (nbase + (off) < nNodes) {                                            \
                float4 r;                                                            \
                r.x = tanhf(cc.x + bias.x);                                          \
                r.y = tanhf(cc.y + bias.y);                                          \
                r.z = tanhf(cc.z + bias.z);                                          \
                r.w = tanhf(cc.w + bias.w);                                          \
                *(float4*)(out + (nbase + (off)) * FEATS + j0) = r;                  \
            }
        STORE_ROW(c0, 0)
        STORE_ROW(c1, 1)
        STORE_ROW(c2, 2)
        STORE_ROW(c3, 3)
        #undef STORE_ROW
    }
}

// ---------------------------------------------------------------------------
// Launcher
// ---------------------------------------------------------------------------
extern "C" void kernel_launch(void* const* d_in, const int* in_sizes, int n_in,
                              void* d_out, int out_size) {
    const float* feature = (const float*)d_in[0];
    const float* W       = (const float*)d_in[1];
    const float* b       = (const float*)d_in[2];
    const void*  src     = d_in[3];
    const void*  dst     = d_in[4];
    float* out = (float*)d_out;

    int nEdges = in_sizes[3];
    int nNodes = out_size / FEATS;

    // 1) zero aggregation scratch
    int zthreads = 256;
    int zblocks = (NN * FEATS / 4 + zthreads - 1) / zthreads;
    zero_agg_kernel<<<zblocks, zthreads>>>();

    // 2) detect index dtype (int32 vs int64)
    detect_idx_kernel<<<1, 1>>>(src);

    // 3) edge scatter-add (one warp per edge)
    int sthreads = 256;
    int swarps = sthreads / 32;
    int sblocks = (nEdges + swarps - 1) / swarps;
    scatter_kernel<<<sblocks, sthreads>>>(feature, src, dst, nEdges);

    // 4) fused GEMM + bias + tanh (persistent blocks)
    cudaFuncSetAttribute(gemm_tanh_kernel,
                         cudaFuncAttributeMaxDynamicSharedMemorySize, GEMM_SMEM);
    gemm_tanh_kernel<<<304, 256, GEMM_SMEM>>>(W, b, out, nNodes);
}

// round 2
// speedup vs baseline: 1.1576x; 1.1576x over previous
#include <cuda_runtime.h>
#include <math.h>

#define NN 50000
#define NE 600000
#define FEATS 128
#define WSH_STRIDE 132
#define TILE_N 32
#define GEMM_SMEM ((128 * WSH_STRIDE + TILE_N * FEATS) * 4)

#define SCAN_CHUNK 512
#define NCHUNK ((NN + SCAN_CHUNK - 1) / SCAN_CHUNK)   // 98

// -------------------- device scratch (no allocations allowed) --------------
__device__ int g_idx64;
__device__ int g_count[NN];
__device__ int g_off[NN + 1];
__device__ int g_cursor[NN];
__device__ int g_btot[128];
__device__ int g_edges[NE];

// packed fp32x2 FMA (sm_103a; ptxas never auto-emits this)
#define FFMA2(d, a, b) \
    asm("fma.rn.f32x2 %0, %1, %2, %0;" : "+l"(d) : "l"(a), "l"(b))
#define PACKDUP(d, x) \
    asm("mov.b64 %0, {%1, %1};" : "=l"(d) : "r"(__float_as_uint(x)))

__device__ __forceinline__ int load_idx(const void* p, int i) {
    return g_idx64 ? (int)((const long long*)p)[i] : ((const int*)p)[i];
}

// ---------------------------------------------------------------------------
// Detect int64 vs int32 index dtype (JAX may silently downcast).
// ---------------------------------------------------------------------------
__global__ void detect_idx_kernel(const void* __restrict__ src) {
    const long long* p = (const long long*)src;
    int is64 = 1;
    for (int i = 0; i < 64; i++) {
        long long v = p[i];
        if (v < 0 || v >= NN) { is64 = 0; break; }
    }
    g_idx64 = is64;
}

// ---------------------------------------------------------------------------
// CSR build: zero counts -> histogram -> 3-phase scan -> fill
// ---------------------------------------------------------------------------
__global__ void zero_counts_kernel() {
    int i = blockIdx.x * blockDim.x + threadIdx.x;
    if (i < NN) g_count[i] = 0;
}

__global__ void hist_kernel(const void* __restrict__ dst, int nE) {
    int i = blockIdx.x * blockDim.x + threadIdx.x;
    if (i < nE) {
        int d = load_idx(dst, i);
        atomicAdd(&g_count[d], 1);
    }
}

// per-chunk exclusive scan; chunk totals -> g_btot
__global__ void scanA_kernel() {
    __shared__ int sh[SCAN_CHUNK];
    int t = threadIdx.x;
    int gid = blockIdx.x * SCAN_CHUNK + t;
    int v = (gid < NN) ? g_count[gid] : 0;
    sh[t] = v;
    __syncthreads();
    for (int ofs = 1; ofs < SCAN_CHUNK; ofs <<= 1) {
        int tmp = (t >= ofs) ? sh[t - ofs] : 0;
        __syncthreads();
        sh[t] += tmp;
        __syncthreads();
    }
    if (gid < NN) g_off[gid] = sh[t] - v;       // exclusive within chunk
    if (t == SCAN_CHUNK - 1) g_btot[blockIdx.x] = sh[t];  // chunk total
}

// exclusive scan of the chunk totals (single block)
__global__ void scanB_kernel() {
    __shared__ int sh[128];
    int t = threadIdx.x;
    int v = (t < NCHUNK) ? g_btot[t] : 0;
    sh[t] = v;
    __syncthreads();
    for (int ofs = 1; ofs < 128; ofs <<= 1) {
        int tmp = (t >= ofs) ? sh[t - ofs] : 0;
        __syncthreads();
        sh[t] += tmp;
        __syncthreads();
    }
    if (t < NCHUNK) g_btot[t] = sh[t] - v;      // exclusive
}

// add chunk prefixes, publish offsets + cursors
__global__ void scanC_kernel(int nE) {
    int t = threadIdx.x;
    int gid = blockIdx.x * SCAN_CHUNK + t;
    int add = g_btot[blockIdx.x];
    if (gid < NN) {
        int o = g_off[gid] + add;
        g_off[gid] = o;
        g_cursor[gid] = o;
    }
    if (blockIdx.x == 0 && t == 0) g_off[NN] = nE;
}

__global__ void fill_kernel(const void* __restrict__ src,
                            const void* __restrict__ dst, int nE) {
    int i = blockIdx.x * blockDim.x + threadIdx.x;
    if (i < nE) {
        int d = load_idx(dst, i);
        int s = load_idx(src, i);
        int pos = atomicAdd(&g_cursor[d], 1);
        g_edges[pos] = s;
    }
}

// ---------------------------------------------------------------------------
// Fused gather + GEMM + bias + tanh. Persistent blocks.
//   smem: Wsh[128][132] (W transposed, conflict-free float4 reads)
//         Ash[32][128]  (gathered agg tile)
//   Gather: warp w accumulates 4 nodes' features in registers (lane = 4 feats)
//   GEMM:   warp computes 4 nodes x 4 cols per lane using packed FFMA2.
// ---------------------------------------------------------------------------
__global__ __launch_bounds__(256) void gcn_fused_kernel(
    const float* __restrict__ feat, const float* __restrict__ W,
    const float* __restrict__ b, float* __restrict__ out, int nNodes) {
    extern __shared__ float sh[];
    float* Wsh = sh;                      // [128][132]
    float* Ash = sh + 128 * WSH_STRIDE;   // [32][128]

    int tid = threadIdx.x;
    int lane = tid & 31;
    int warp = tid >> 5;
    int j0 = lane * 4;
    int lane4 = lane * 4;

    // Load W transposed: Wsh[k][j] = W[j][k]
    for (int idx = tid; idx < 128 * 128; idx += 256) {
        int j = idx >> 7;
        int k = idx & 127;
        Wsh[k * WSH_STRIDE + j] = W[idx];
    }

    float4 bias = *(const float4*)(b + j0);

    for (int tile = blockIdx.x * TILE_N; tile < nNodes; tile += gridDim.x * TILE_N) {
        __syncthreads();  // Ash reuse barrier (also orders Wsh load on iter 0)

        // ---- gather: warp handles 4 nodes, lane holds float4 of feats ----
        #pragma unroll
        for (int r = 0; r < 4; r++) {
            int node = tile + warp * 4 + r;
            float4 acc = make_float4(0.f, 0.f, 0.f, 0.f);
            if (node < nNodes) {
                int e = g_off[node];
                int e1 = g_off[node + 1];
                for (; e + 4 <= e1; e += 4) {
                    int s0 = g_edges[e], s1 = g_edges[e + 1];
                    int s2 = g_edges[e + 2], s3 = g_edges[e + 3];
                    float4 f0 = *(const float4*)(feat + (long)s0 * FEATS + lane4);
                    float4 f1 = *(const float4*)(feat + (long)s1 * FEATS + lane4);
                    float4 f2 = *(const float4*)(feat + (long)s2 * FEATS + lane4);
                    float4 f3 = *(const float4*)(feat + (long)s3 * FEATS + lane4);
                    float4 p, q;
                    p.x = f0.x + f1.x; p.y = f0.y + f1.y;
                    p.z = f0.z + f1.z; p.w = f0.w + f1.w;
                    q.x = f2.x + f3.x; q.y = f2.y + f3.y;
                    q.z = f2.z + f3.z; q.w = f2.w + f3.w;
                    acc.x += p.x + q.x; acc.y += p.y + q.y;
                    acc.z += p.z + q.z; acc.w += p.w + q.w;
                }
                for (; e < e1; e++) {
                    int s = g_edges[e];
                    float4 f = *(const float4*)(feat + (long)s * FEATS + lane4);
                    acc.x += f.x; acc.y += f.y; acc.z += f.z; acc.w += f.w;
                }
            }
            *(float4*)(Ash + (warp * 4 + r) * FEATS + lane4) = acc;
        }
        __syncthreads();

        // ---- GEMM: 4 nodes x 4 cols per lane, packed f32x2 FMA ----
        const float* a0 = Ash + (warp * 4 + 0) * FEATS;
        const float* a1 = a0 + FEATS;
        const float* a2 = a1 + FEATS;
        const float* a3 = a2 + FEATS;

        unsigned long long c00 = 0, c01 = 0, c10 = 0, c11 = 0;
        unsigned long long c20 = 0, c21 = 0, c30 = 0, c31 = 0;

        #pragma unroll 4
        for (int k4 = 0; k4 < FEATS; k4 += 4) {
            float4 x0 = *(const float4*)(a0 + k4);
            float4 x1 = *(const float4*)(a1 + k4);
            float4 x2 = *(const float4*)(a2 + k4);
            float4 x3 = *(const float4*)(a3 + k4);
            const float* xv0 = (const float*)&x0;
            const float* xv1 = (const float*)&x1;
            const float* xv2 = (const float*)&x2;
            const float* xv3 = (const float*)&x3;
            #pragma unroll
            for (int kk = 0; kk < 4; kk++) {
                ulonglong2 wv =
                    *(const ulonglong2*)(Wsh + (k4 + kk) * WSH_STRIDE + j0);
                unsigned long long d0, d1, d2, d3;
                PACKDUP(d0, xv0[kk]);
                PACKDUP(d1, xv1[kk]);
                PACKDUP(d2, xv2[kk]);
                PACKDUP(d3, xv3[kk]);
                FFMA2(c00, wv.x, d0); FFMA2(c01, wv.y, d0);
                FFMA2(c10, wv.x, d1); FFMA2(c11, wv.y, d1);
                FFMA2(c20, wv.x, d2); FFMA2(c21, wv.y, d2);
                FFMA2(c30, wv.x, d3); FFMA2(c31, wv.y, d3);
            }
        }

        int nbase = tile + warp * 4;
        #define STORE_ROW(cA, cB, off)                                        \
            if (nbase + (off) < nNodes) {                                     \
                float2 lo = *(float2*)&cA;                                    \
                float2 hi = *(float2*)&cB;                                    \
                float4 r;                                                     \
                r.x = tanhf(lo.x + bias.x);                                   \
                r.y = tanhf(lo.y + bias.y);                                   \
                r.z = tanhf(hi.x + bias.z);                                   \
                r.w = tanhf(hi.y + bias.w);                                   \
                *(float4*)(out + (long)(nbase + (off)) * FEATS + j0) = r;     \
            }
        STORE_ROW(c00, c01, 0)
        STORE_ROW(c10, c11, 1)
        STORE_ROW(c20, c21, 2)
        STORE_ROW(c30, c31, 3)
        #undef STORE_ROW
    }
}

// ---------------------------------------------------------------------------
// Launcher
// ---------------------------------------------------------------------------
extern "C" void kernel_launch(void* const* d_in, const int* in_sizes, int n_in,
                              void* d_out, int out_size) {
    const float* feature = (const float*)d_in[0];
    const float* W       = (const float*)d_in[1];
    const float* b       = (const float*)d_in[2];
    const void*  src     = d_in[3];
    const void*  dst     = d_in[4];
    float* out = (float*)d_out;

    int nEdges = in_sizes[3];
    int nNodes = out_size / FEATS;

    detect_idx_kernel<<<1, 1>>>(src);

    // CSR build
    zero_counts_kernel<<<(NN + 255) / 256, 256>>>();
    hist_kernel<<<(nEdges + 255) / 256, 256>>>(dst, nEdges);
    scanA_kernel<<<NCHUNK, SCAN_CHUNK>>>();
    scanB_kernel<<<1, 128>>>();
    scanC_kernel<<<NCHUNK, SCAN_CHUNK>>>(nEdges);
    fill_kernel<<<(nEdges + 255) / 256, 256>>>(src, dst, nEdges);

    // fused gather + GEMM + tanh (persistent, 2 blocks/SM)
    cudaFuncSetAttribute(gcn_fused_kernel,
                         cudaFuncAttributeMaxDynamicSharedMemorySize, GEMM_SMEM);
    gcn_fused_kernel<<<296, 256, GEMM_SMEM>>>(feature, W, b, out, nNodes);
}

// round 3
// speedup vs baseline: 1.3582x; 1.1733x over previous
#include <cuda_runtime.h>
#include <math.h>

#define NN 50000
#define NE 600000
#define FEATS 128
#define WSH_STRIDE 132
#define TILE_N 32
#define ESH_CAP 4096

// smem: Wsh[128][132] + Ash[32][128] + Esh[4096] + Osh[64]
#define GEMM_SMEM ((128 * WSH_STRIDE + TILE_N * FEATS) * 4 + ESH_CAP * 4 + 64 * 4)

#define SCAN_CHUNK 1024
#define NCHUNK ((NN + SCAN_CHUNK - 1) / SCAN_CHUNK)   // 49

// -------------------- device scratch (no allocations allowed) --------------
__device__ int g_idx64;
__device__ int g_count[NN];
__device__ int g_off[NN + 1];
__device__ int g_cursor[NN];
__device__ int g_btot[128];
__device__ int g_edges[NE];

// packed fp32x2 FMA (sm_103a; ptxas never auto-emits this)
#define FFMA2(d, a, b) \
    asm("fma.rn.f32x2 %0, %1, %2, %0;" : "+l"(d) : "l"(a), "l"(b))
#define PACKDUP(d, x) \
    asm("mov.b64 %0, {%1, %1};" : "=l"(d) : "r"(__float_as_uint(x)))

__device__ __forceinline__ int load_idx(const void* p, int i) {
    return g_idx64 ? (int)((const long long*)p)[i] : ((const int*)p)[i];
}

// ---------------------------------------------------------------------------
__global__ void detect_idx_kernel(const void* __restrict__ src) {
    const long long* p = (const long long*)src;
    int is64 = 1;
    for (int i = 0; i < 64; i++) {
        long long v = p[i];
        if (v < 0 || v >= NN) { is64 = 0; break; }
    }
    g_idx64 = is64;
}

__global__ void zero_counts_kernel() {
    int i = blockIdx.x * blockDim.x + threadIdx.x;
    if (i < NN) g_count[i] = 0;
}

__global__ void hist_kernel(const void* __restrict__ dst, int nE) {
    int i = blockIdx.x * blockDim.x + threadIdx.x;
    if (i < nE) {
        int d = load_idx(dst, i);
        atomicAdd(&g_count[d], 1);
    }
}

// ---- shuffle-based chunk scan (1024 elems/block, 2 barriers) --------------
__global__ void scanA_kernel() {
    __shared__ int wsum[32];
    int t = threadIdx.x;
    int lane = t & 31, wid = t >> 5;
    int gid = blockIdx.x * SCAN_CHUNK + t;
    int v = (gid < NN) ? g_count[gid] : 0;
    int x = v;
    #pragma unroll
    for (int o = 1; o < 32; o <<= 1) {
        int y = __shfl_up_sync(0xffffffff, x, o);
        if (lane >= o) x += y;
    }
    if (lane == 31) wsum[wid] = x;
    __syncthreads();
    if (wid == 0) {
        int s = (lane < 32) ? wsum[lane] : 0;
        #pragma unroll
        for (int o = 1; o < 32; o <<= 1) {
            int y = __shfl_up_sync(0xffffffff, s, o);
            if (lane >= o) s += y;
        }
        wsum[lane] = s;
    }
    __syncthreads();
    int pre = (wid > 0) ? wsum[wid - 1] : 0;
    int incl = x + pre;
    if (gid < NN) g_off[gid] = incl - v;                 // exclusive
    if (t == SCAN_CHUNK - 1) g_btot[blockIdx.x] = incl;  // chunk total
}

__global__ void scanB_kernel() {
    __shared__ int sh[64];
    int t = threadIdx.x;
    int v = (t < NCHUNK) ? g_btot[t] : 0;
    sh[t] = v;
    __syncthreads();
    for (int o = 1; o < 64; o <<= 1) {
        int tmp = (t >= o) ? sh[t - o] : 0;
        __syncthreads();
        sh[t] += tmp;
        __syncthreads();
    }
    if (t < NCHUNK) g_btot[t] = sh[t] - v;
}

__global__ void scanC_kernel(int nE) {
    int t = threadIdx.x;
    int gid = blockIdx.x * SCAN_CHUNK + t;
    int add = g_btot[blockIdx.x];
    if (gid < NN) {
        int o = g_off[gid] + add;
        g_off[gid] = o;
        g_cursor[gid] = o;
    }
    if (blockIdx.x == 0 && t == 0) g_off[NN] = nE;
}

__global__ void fill_kernel(const void* __restrict__ src,
                            const void* __restrict__ dst, int nE) {
    int i = blockIdx.x * blockDim.x + threadIdx.x;
    if (i < nE) {
        int d = load_idx(dst, i);
        int s = load_idx(src, i);
        int pos = atomicAdd(&g_cursor[d], 1);
        g_edges[pos] = s;
    }
}

// ---------------------------------------------------------------------------
// Fused gather + GEMM + bias + tanh. Persistent blocks, 2/SM.
// Gather: edge indices staged in smem; predicated unroll-8 feature loads;
// all 4 node accumulators stored at the end (one latency drain per tile).
// GEMM: packed f32x2 FMA, 4 nodes x 4 cols per lane.
// ---------------------------------------------------------------------------
__global__ __launch_bounds__(256, 2) void gcn_fused_kernel(
    const float* __restrict__ feat, const float* __restrict__ W,
    const float* __restrict__ b, float* __restrict__ out, int nNodes) {
    extern __shared__ float sh[];
    float* Wsh = sh;                                  // [128][132]
    float* Ash = sh + 128 * WSH_STRIDE;               // [32][128]
    int*   Esh = (int*)(Ash + TILE_N * FEATS);        // [4096]
    int*   Osh = Esh + ESH_CAP;                       // [64]

    int tid = threadIdx.x;
    int lane = tid & 31;
    int warp = tid >> 5;
    int j0 = lane * 4;
    int lane4 = lane * 4;

    // Load W transposed: Wsh[k][j] = W[j][k]
    for (int idx = tid; idx < 128 * 128; idx += 256) {
        int j = idx >> 7;
        int k = idx & 127;
        Wsh[k * WSH_STRIDE + j] = W[idx];
    }

    float4 bias = *(const float4*)(b + j0);

    for (int tile = blockIdx.x * TILE_N; tile < nNodes; tile += gridDim.x * TILE_N) {
        __syncthreads();   // Ash/Esh reuse barrier (covers Wsh load on iter 0)

        // ---- stage per-node offsets + edge indices ----
        int tend = tile + TILE_N;
        if (tend > nNodes) tend = nNodes;
        int e0t = __ldg(&g_off[tile]);
        int e1t = __ldg(&g_off[tend]);
        int cnt = e1t - e0t;
        bool staged = (cnt <= ESH_CAP);
        if (tid <= TILE_N) {
            int nd = tile + tid;
            if (nd > nNodes) nd = nNodes;
            Osh[tid] = g_off[nd];
        }
        if (staged) {
            for (int i = tid; i < cnt; i += 256) Esh[i] = g_edges[e0t + i];
        }
        __syncthreads();

        // ---- gather: warp handles 4 nodes, lane holds float4 of feats ----
        float4 acc[4];
        #pragma unroll
        for (int r = 0; r < 4; r++) acc[r] = make_float4(0.f, 0.f, 0.f, 0.f);

        #define GATHER_LOOP(IDXP)                                              \
            _Pragma("unroll")                                                  \
            for (int r = 0; r < 4; r++) {                                      \
                int node = tile + warp * 4 + r;                                \
                if (node < nNodes) {                                           \
                    int eb = Osh[warp * 4 + r] - e0t;                          \
                    int ee = Osh[warp * 4 + r + 1] - e0t;                      \
                    for (int e = eb; e < ee; e += 8) {                         \
                        _Pragma("unroll")                                      \
                        for (int u = 0; u < 8; u++) {                          \
                            int j = e + u;                                     \
                            int s = (IDXP)[j < ee ? j : eb];                   \
                            float4 f = *(const float4*)(feat +                 \
                                          (long)s * FEATS + lane4);            \
                            if (j < ee) {                                      \
                                acc[r].x += f.x; acc[r].y += f.y;              \
                                acc[r].z += f.z; acc[r].w += f.w;              \
                            }                                                  \
                        }                                                      \
                    }                                                          \
                }                                                              \
            }

        if (staged) {
            GATHER_LOOP(Esh)
        } else {
            const int* gp = g_edges + e0t;
            GATHER_LOOP(gp)
        }
        #undef GATHER_LOOP

        // single latency drain: store all 4 accumulators
        #pragma unroll
        for (int r = 0; r < 4; r++)
            *(float4*)(Ash + (warp * 4 + r) * FEATS + lane4) = acc[r];
        __syncthreads();

        // ---- GEMM: 4 nodes x 4 cols per lane, packed f32x2 FMA ----
        const float* a0 = Ash + (warp * 4 + 0) * FEATS;
        const float* a1 = a0 + FEATS;
        const float* a2 = a1 + FEATS;
        const float* a3 = a2 + FEATS;

        unsigned long long c00 = 0, c01 = 0, c10 = 0, c11 = 0;
        unsigned long long c20 = 0, c21 = 0, c30 = 0, c31 = 0;

        #pragma unroll 4
        for (int k4 = 0; k4 < FEATS; k4 += 4) {
            float4 x0 = *(const float4*)(a0 + k4);
            float4 x1 = *(const float4*)(a1 + k4);
            float4 x2 = *(const float4*)(a2 + k4);
            float4 x3 = *(const float4*)(a3 + k4);
            const float* xv0 = (const float*)&x0;
            const float* xv1 = (const float*)&x1;
            const float* xv2 = (const float*)&x2;
            const float* xv3 = (const float*)&x3;
            #pragma unroll
            for (int kk = 0; kk < 4; kk++) {
                ulonglong2 wv =
                    *(const ulonglong2*)(Wsh + (k4 + kk) * WSH_STRIDE + j0);
                unsigned long long d0, d1, d2, d3;
                PACKDUP(d0, xv0[kk]);
                PACKDUP(d1, xv1[kk]);
                PACKDUP(d2, xv2[kk]);
                PACKDUP(d3, xv3[kk]);
                FFMA2(c00, wv.x, d0); FFMA2(c01, wv.y, d0);
                FFMA2(c10, wv.x, d1); FFMA2(c11, wv.y, d1);
                FFMA2(c20, wv.x, d2); FFMA2(c21, wv.y, d2);
                FFMA2(c30, wv.x, d3); FFMA2(c31, wv.y, d3);
            }
        }

        int nbase = tile + warp * 4;
        #define STORE_ROW(cA, cB, off)                                        \
            if (nbase + (off) < nNodes) {                                     \
                float2 lo = *(float2*)&cA;                                    \
                float2 hi = *(float2*)&cB;                                    \
                float4 r;                                                     \
                r.x = tanhf(lo.x + bias.x);                                   \
                r.y = tanhf(lo.y + bias.y);                                   \
                r.z = tanhf(hi.x + bias.z);                                   \
                r.w = tanhf(hi.y + bias.w);                                   \
                *(float4*)(out + (long)(nbase + (off)) * FEATS + j0) = r;     \
            }
        STORE_ROW(c00, c01, 0)
        STORE_ROW(c10, c11, 1)
        STORE_ROW(c20, c21, 2)
        STORE_ROW(c30, c31, 3)
        #undef STORE_ROW
    }
}

// ---------------------------------------------------------------------------
extern "C" void kernel_launch(void* const* d_in, const int* in_sizes, int n_in,
                              void* d_out, int out_size) {
    const float* feature = (const float*)d_in[0];
    const float* W       = (const float*)d_in[1];
    const float* b       = (const float*)d_in[2];
    const void*  src     = d_in[3];
    const void*  dst     = d_in[4];
    float* out = (float*)d_out;

    int nEdges = in_sizes[3];
    int nNodes = out_size / FEATS;

    detect_idx_kernel<<<1, 1>>>(src);

    zero_counts_kernel<<<(NN + 255) / 256, 256>>>();
    hist_kernel<<<(nEdges + 255) / 256, 256>>>(dst, nEdges);
    scanA_kernel<<<NCHUNK, SCAN_CHUNK>>>();
    scanB_kernel<<<1, 64>>>();
    scanC_kernel<<<NCHUNK, SCAN_CHUNK>>>(nEdges);
    fill_kernel<<<(nEdges + 255) / 256, 256>>>(src, dst, nEdges);

    cudaFuncSetAttribute(gcn_fused_kernel,
                         cudaFuncAttributeMaxDynamicSharedMemorySize, GEMM_SMEM);
    gcn_fused_kernel<<<296, 256, GEMM_SMEM>>>(feature, W, b, out, nNodes);
}